// round 16
// baseline (speedup 1.0000x reference)
#include <cuda_runtime.h>
#include <cuda_bf16.h>
#include <mma.h>
using namespace nvcuda;

#define BB 4
#define CC 64
#define DWC 128
#define HH 256
#define WW 256
#define HWP (HH*WW)
#define HWP2 (HWP/2)
#define EPSF 1e-6f

typedef unsigned long long u64;
typedef unsigned int u32;

static __device__ __forceinline__ u32 pack_bf16(float lo, float hi) {
    u32 r;
    asm("cvt.rn.bf16x2.f32 %0, %1, %2;" : "=r"(r) : "f"(hi), "f"(lo));
    return r;
}
static __device__ __forceinline__ float2 bf16pair_to_f2(u32 v) {
    __nv_bfloat162 b = *reinterpret_cast<__nv_bfloat162*>(&v);
    return __bfloat1622float2(b);
}
static __device__ __forceinline__ float topk_gate(const float* probs, int b, int& be) {
    float best = probs[b*3]; be = 0;
    #pragma unroll
    for (int e = 1; e < 3; e++) {
        float p = probs[b*3+e];
        if (p > best) { best = p; be = e; }
    }
    return best * 2.0f;  // gate * SCALING
}

// ---------------- device scratch ----------------
__device__ u32 g_w1b[BB][DWC][32];      // conv1 eff weights, bf16 pairs [oc][k/2]
__device__ u32 g_w3b[BB][CC][32];
__device__ u32 g_w4b[BB][DWC][32];
__device__ u32 g_w5b[BB][CC][32];
__device__ float g_wscaf[BB][CC][CC];   // sca eff weights fp32
__device__ u32 g_u[BB][DWC][HWP2];      // conv1 out, bf16 pairs (64 MB)
__device__ u32 g_t[BB][CC][HWP2];       // gated out, bf16 pairs (32 MB)
__device__ float g_poolpart[BB][CC][32];

// ---------------- K0: gate + effective weights (bf16) ----------------
__global__ void k0_weights(const float* __restrict__ probs,
    const float* __restrict__ w1, const float* __restrict__ la1, const float* __restrict__ lb1,
    const float* __restrict__ w3, const float* __restrict__ la3, const float* __restrict__ lb3,
    const float* __restrict__ w4, const float* __restrict__ la4, const float* __restrict__ lb4,
    const float* __restrict__ w5, const float* __restrict__ la5, const float* __restrict__ lb5,
    const float* __restrict__ wsca, const float* __restrict__ lasca, const float* __restrict__ lbsca)
{
    int b = blockIdx.x, t = threadIdx.x;
    int be; float g = topk_gate(probs, b, be);

    for (int idx = t; idx < DWC*32; idx += 256) {
        int o = idx >> 5, p = idx & 31;
        int i0 = 2*p, i1 = 2*p+1;
        float e10 = 0.f, e11 = 0.f, e40 = 0.f, e41 = 0.f;
        #pragma unroll
        for (int r = 0; r < 4; r++) {
            float lbv1 = lb1[(be*DWC+o)*4+r], lbv4 = lb4[(be*DWC+o)*4+r];
            e10 += lbv1 * la1[(be*4+r)*CC+i0];
            e11 += lbv1 * la1[(be*4+r)*CC+i1];
            e40 += lbv4 * la4[(be*4+r)*CC+i0];
            e41 += lbv4 * la4[(be*4+r)*CC+i1];
        }
        g_w1b[b][o][p] = pack_bf16(w1[o*CC+i0] + g*e10, w1[o*CC+i1] + g*e11);
        g_w4b[b][o][p] = pack_bf16(w4[o*CC+i0] + g*e40, w4[o*CC+i1] + g*e41);
    }
    for (int idx = t; idx < CC*32; idx += 256) {
        int o = idx >> 5, p = idx & 31;
        int i0 = 2*p, i1 = 2*p+1;
        float e30 = 0.f, e31 = 0.f, e50 = 0.f, e51 = 0.f;
        #pragma unroll
        for (int r = 0; r < 4; r++) {
            float lbv3 = lb3[(be*CC+o)*4+r], lbv5 = lb5[(be*CC+o)*4+r];
            e30 += lbv3 * la3[(be*4+r)*CC+i0];
            e31 += lbv3 * la3[(be*4+r)*CC+i1];
            e50 += lbv5 * la5[(be*4+r)*CC+i0];
            e51 += lbv5 * la5[(be*4+r)*CC+i1];
        }
        g_w3b[b][o][p] = pack_bf16(w3[o*CC+i0] + g*e30, w3[o*CC+i1] + g*e31);
        g_w5b[b][o][p] = pack_bf16(w5[o*CC+i0] + g*e50, w5[o*CC+i1] + g*e51);
    }
    for (int idx = t; idx < CC*CC; idx += 256) {
        int o = idx >> 6, i = idx & 63;
        float s = 0.f;
        #pragma unroll
        for (int r = 0; r < 4; r++)
            s += lbsca[(be*CC+o)*4+r] * lasca[(be*4+r)*CC+i];
        g_wscaf[b][o][i] = wsca[idx] + g*s;
    }
}

// ---------------- K1: LN1 + conv1 (64->128) via wmma, 128-pix tiles ----------------
#define XB_LD 136
#define W_LD 72

__global__ __launch_bounds__(256) void k1_ln_conv1(
    const float* __restrict__ inp, const float* __restrict__ ln1w,
    const float* __restrict__ ln1b, const float* __restrict__ b1)
{
    extern __shared__ char smraw[];
    __nv_bfloat16* w1s = (__nv_bfloat16*)smraw;            // [128][72]
    __nv_bfloat16* xb  = w1s + DWC*W_LD;                   // [64][136]
    float* stg  = (float*)(xb + CC*XB_LD);                 // [8][256]
    float* psum = stg + 8*256;
    float* psq  = psum + 256;
    float* mu   = psq + 256;
    float* rstd = mu + 128;
    float* bias1 = rstd + 128;
    float* lnw  = bias1 + 128;
    float* lnb  = lnw + 64;

    int b = blockIdx.y;
    int pixbase = blockIdx.x * 128;
    int t = threadIdx.x;
    int pix = t & 127, crow = t >> 7;

    const float* X = inp + (size_t)b*CC*HWP + pixbase;
    float vreg[32];
    float s = 0.f, sq = 0.f;
    #pragma unroll
    for (int i = 0; i < 32; i++) {
        int c = crow + 2*i;
        float v = X[(size_t)c*HWP + pix];
        vreg[i] = v; s += v; sq += v*v;
    }
    psum[crow*128+pix] = s; psq[crow*128+pix] = sq;

    u32* w1su = (u32*)w1s;
    for (int idx = t; idx < DWC*32; idx += 256) {
        int o = idx >> 5, p = idx & 31;
        w1su[o*36 + p] = g_w1b[b][o][p];
    }
    if (t < 128) bias1[t] = b1[t];
    if (t < 64) { lnw[t] = ln1w[t]; lnb[t] = ln1b[t]; }
    __syncthreads();

    if (t < 128) {
        float m = (psum[t]+psum[128+t]) * (1.f/CC);
        float var = (psq[t]+psq[128+t]) * (1.f/CC) - m*m;
        mu[t] = m; rstd[t] = rsqrtf(var + EPSF);
    }
    __syncthreads();

    float mpix = mu[pix], rpix = rstd[pix];
    #pragma unroll
    for (int i = 0; i < 32; i++) {
        int c = crow + 2*i;
        xb[c*XB_LD + pix] = __float2bfloat16((vreg[i]-mpix)*rpix*lnw[c] + lnb[c]);
    }
    __syncthreads();

    int w = t >> 5, lane = t & 31;
    wmma::fragment<wmma::matrix_a, 16, 16, 16, __nv_bfloat16, wmma::row_major> af[4];
    #pragma unroll
    for (int kt = 0; kt < 4; kt++)
        wmma::load_matrix_sync(af[kt], w1s + (w*16)*W_LD + kt*16, W_LD);
    float* stgw = stg + w*256;

    for (int pc = 0; pc < 8; pc++) {
        wmma::fragment<wmma::accumulator, 16, 16, 16, float> acc;
        wmma::fill_fragment(acc, 0.f);
        #pragma unroll
        for (int kt = 0; kt < 4; kt++) {
            wmma::fragment<wmma::matrix_b, 16, 16, 16, __nv_bfloat16, wmma::row_major> bf;
            wmma::load_matrix_sync(bf, xb + (kt*16)*XB_LD + pc*16, XB_LD);
            wmma::mma_sync(acc, af[kt], bf, acc);
        }
        wmma::store_matrix_sync(stgw, acc, 16, wmma::mem_row_major);
        __syncwarp();
        int colbase = (pixbase >> 1) + pc*8;
        #pragma unroll
        for (int j = 0; j < 4; j++) {
            int lin = lane*4 + j;
            int row = lin >> 3, pr = lin & 7;
            float bb = bias1[w*16 + row];
            g_u[b][w*16+row][colbase + pr] =
                pack_bf16(stgw[row*16 + 2*pr] + bb, stgw[row*16 + 2*pr + 1] + bb);
        }
        __syncwarp();
    }
}

// ---------------- K2: depthwise 3x3 + SimpleGate + pool partials ----------------
__global__ __launch_bounds__(256) void k2_dw_gate_pool(
    const float* __restrict__ probs,
    const float* __restrict__ w2, const float* __restrict__ la2, const float* __restrict__ lb2,
    const float* __restrict__ b2)
{
    __shared__ float u0[10*258];
    __shared__ float u1[10*258];
    __shared__ float wsm[18];
    __shared__ float redbuf[8];
    int b = blockIdx.z, j = blockIdx.y;
    int r0 = blockIdx.x * 8;
    int t = threadIdx.x;
    int be; float g = topk_gate(probs, b, be);

    if (t < 18) {
        int ch = (t < 9) ? j : (j + CC);
        int kk = t % 9, kh = kk / 3, kw = kk % 3;
        float s = 0.f;
        #pragma unroll
        for (int r = 0; r < 12; r++)
            s += lb2[(be*384 + ch*3 + kh)*12 + r] * la2[(be*12+r)*3 + kw];
        wsm[t] = w2[ch*9 + kk] + g*s;
    }

    const u32* U0 = g_u[b][j];
    const u32* U1 = g_u[b][j+CC];
    for (int idx = t; idx < 10*128; idx += 256) {
        int rr = idx >> 7, cp = idx & 127;
        int row = r0 - 1 + rr;
        float2 v0 = make_float2(0.f, 0.f), v1 = v0;
        if (row >= 0 && row < HH) {
            v0 = bf16pair_to_f2(U0[row*128 + cp]);
            v1 = bf16pair_to_f2(U1[row*128 + cp]);
        }
        u0[rr*258 + 1 + 2*cp] = v0.x; u0[rr*258 + 2 + 2*cp] = v0.y;
        u1[rr*258 + 1 + 2*cp] = v1.x; u1[rr*258 + 2 + 2*cp] = v1.y;
    }
    if (t < 10) { u0[t*258] = 0.f; u1[t*258] = 0.f; }
    else if (t < 20) { int rr = t-10; u0[rr*258+257] = 0.f; u1[rr*258+257] = 0.f; }
    __syncthreads();

    float wa[9], wb[9];
    #pragma unroll
    for (int i = 0; i < 9; i++) { wa[i] = wsm[i]; wb[i] = wsm[9+i]; }
    float biasA = b2[j], biasB = b2[j+CC];

    int cp = t & 127, rg = t >> 7;
    int c0 = 2*cp;
    float lsum = 0.f;
    #pragma unroll
    for (int ii = 0; ii < 4; ii++) {
        int orow = rg*4 + ii;
        float a0 = biasA, a1 = biasA, c0v = biasB, c1v = biasB;
        #pragma unroll
        for (int kh = 0; kh < 3; kh++) {
            const float* r0p = u0 + (orow+kh)*258 + c0;
            const float* r1p = u1 + (orow+kh)*258 + c0;
            float2 x01 = *(const float2*)r0p;
            float2 x23 = *(const float2*)(r0p+2);
            float2 y01 = *(const float2*)r1p;
            float2 y23 = *(const float2*)(r1p+2);
            a0 = fmaf(wa[kh*3+0], x01.x, a0); a0 = fmaf(wa[kh*3+1], x01.y, a0); a0 = fmaf(wa[kh*3+2], x23.x, a0);
            a1 = fmaf(wa[kh*3+0], x01.y, a1); a1 = fmaf(wa[kh*3+1], x23.x, a1); a1 = fmaf(wa[kh*3+2], x23.y, a1);
            c0v = fmaf(wb[kh*3+0], y01.x, c0v); c0v = fmaf(wb[kh*3+1], y01.y, c0v); c0v = fmaf(wb[kh*3+2], y23.x, c0v);
            c1v = fmaf(wb[kh*3+0], y01.y, c1v); c1v = fmaf(wb[kh*3+1], y23.x, c1v); c1v = fmaf(wb[kh*3+2], y23.y, c1v);
        }
        float p0v = a0 * c0v, p1v = a1 * c1v;
        g_t[b][j][(r0+orow)*128 + cp] = pack_bf16(p0v, p1v);
        lsum += p0v + p1v;
    }
    #pragma unroll
    for (int off = 16; off > 0; off >>= 1) lsum += __shfl_down_sync(0xffffffffu, lsum, off);
    if ((t & 31) == 0) redbuf[t >> 5] = lsum;
    __syncthreads();
    if (t == 0) {
        float tot = 0.f;
        #pragma unroll
        for (int i = 0; i < 8; i++) tot += redbuf[i];
        g_poolpart[b][j][blockIdx.x] = tot;
    }
}

// ---------------- K4 v3: 128-pix tiles, weights from global, gate fused, 3 CTA/SM ----------------
#define TP4 128
#define D_LD 136   // bf16 stride for xb/Dst
#define D_LDU 68   // u32 stride

__global__ __launch_bounds__(256, 3) void k4_final(
    const float* __restrict__ inp,
    const float* __restrict__ bsca,
    const float* __restrict__ b3, const float* __restrict__ b4, const float* __restrict__ b5,
    const float* __restrict__ ln2w, const float* __restrict__ ln2b,
    const float* __restrict__ beta, const float* __restrict__ gamma,
    float* __restrict__ out)
{
    extern __shared__ char smraw[];
    __nv_bfloat16* xb  = (__nv_bfloat16*)smraw;    // [64][136]
    __nv_bfloat16* Dst = xb + CC*D_LD;             // [64][136]
    float* stg  = (float*)(Dst + CC*D_LD);         // [8][512]
    float* mu   = stg + 8*512;                     // 128
    float* rstd = mu + 128;                        // 128
    float* redS = rstd + 128;                      // 256
    float* redQ = redS + 256;                      // 256
    float* scas = redQ + 256;                      // 64
    float* pl   = scas + 64;                       // 64
    float* sb3  = pl + 64;                         // 64
    float* sb4  = sb3 + 64;                        // 128
    float* sb5  = sb4 + 128;                       // 64
    float* sbeta = sb5 + 64;                       // 64
    float* sgamma = sbeta + 64;                    // 64
    float* slnw = sgamma + 64;                     // 64
    float* slnb = slnw + 64;                       // 64

    int b = blockIdx.y;
    int pixbase = blockIdx.x * TP4;
    int t = threadIdx.x;
    int w = t >> 5, lane = t & 31;
    int px = t & 127, h = t >> 7;   // elementwise map

    u32* xbu = (u32*)xb;  u32* dstu = (u32*)Dst;
    const __nv_bfloat16* W3 = (const __nv_bfloat16*)g_w3b[b];  // [64][64], ldm 64
    const __nv_bfloat16* W4 = (const __nv_bfloat16*)g_w4b[b];  // [128][64]
    const __nv_bfloat16* W5 = (const __nv_bfloat16*)g_w5b[b];  // [64][64]

    // constants + pooled sums
    if (t < 64) {
        float s = 0.f;
        #pragma unroll
        for (int p = 0; p < 32; p++) s += g_poolpart[b][t][p];
        pl[t] = s;
        sb3[t] = b3[t]; sb5[t] = b5[t];
        sbeta[t] = beta[t]; sgamma[t] = gamma[t];
        slnw[t] = ln2w[t]; slnb[t] = ln2b[t];
    }
    if (t < 128) sb4[t] = b4[t];
    __syncthreads();

    if (t < 64) {
        float acc = 0.f;
        #pragma unroll 8
        for (int i = 0; i < CC; i++) acc += g_wscaf[b][t][i] * pl[i];
        scas[t] = bsca[t] + acc * (1.f/HWP);
    }
    __syncthreads();

    // xb = bf16(t * sca)
    int prb = pixbase >> 1;
    for (int idx = t; idx < CC*64; idx += 256) {
        int c = idx >> 6, pr = idx & 63;
        float2 f = bf16pair_to_f2(g_t[b][c][prb + pr]);
        float sc = scas[c];
        xbu[c*D_LDU + pr] = pack_bf16(f.x*sc, f.y*sc);
    }
    __syncthreads();

    float* stgw = stg + w*512;
    int r = w & 3;
    int pc0 = (w >> 2)*4;

    // ---- conv3 (64->64): A from global, B=xb, out -> Dst
    #pragma unroll
    for (int pi = 0; pi < 4; pi++) {
        int pc = pc0 + pi;
        wmma::fragment<wmma::accumulator, 16, 16, 16, float> acc;
        wmma::fill_fragment(acc, 0.f);
        #pragma unroll
        for (int kt = 0; kt < 4; kt++) {
            wmma::fragment<wmma::matrix_a, 16, 16, 16, __nv_bfloat16, wmma::row_major> af;
            wmma::fragment<wmma::matrix_b, 16, 16, 16, __nv_bfloat16, wmma::row_major> bf;
            wmma::load_matrix_sync(af, W3 + (r*16)*64 + kt*16, 64);
            wmma::load_matrix_sync(bf, xb + (kt*16)*D_LD + pc*16, D_LD);
            wmma::mma_sync(acc, af, bf, acc);
        }
        wmma::store_matrix_sync(stgw, acc, 16, wmma::mem_row_major);
        __syncwarp();
        #pragma unroll
        for (int j = 0; j < 4; j++) {
            int lin = lane*4 + j;
            int row = lin >> 3, pr = lin & 7;
            dstu[(r*16+row)*D_LDU + pc*8 + pr] =
                pack_bf16(stgw[row*16 + 2*pr], stgw[row*16 + 2*pr + 1]);
        }
        __syncwarp();
    }
    __syncthreads();

    // y = inp + (conv3 + b3) * beta   (y in registers; LN2 partials)
    float yreg[32];
    {
        const float* IP = inp + ((size_t)(b*CC + h*32))*HWP + pixbase + px;
        float s = 0.f, sq = 0.f;
        #pragma unroll
        for (int i = 0; i < 32; i++) {
            int c = h*32 + i;
            float d = __bfloat162float(Dst[c*D_LD + px]);
            float yv = IP[(size_t)i*HWP] + (d + sb3[c]) * sbeta[c];
            yreg[i] = yv; s += yv; sq += yv*yv;
        }
        redS[h*128 + px] = s; redQ[h*128 + px] = sq;
    }
    __syncthreads();
    if (t < 128) {
        float s  = redS[t] + redS[128+t];
        float sq = redQ[t] + redQ[128+t];
        float m = s * (1.f/CC);
        float var = sq * (1.f/CC) - m*m;
        mu[t] = m; rstd[t] = rsqrtf(var + EPSF);
    }
    __syncthreads();

    // xb = bf16(ln2(y))
    {
        float m = mu[px], rs = rstd[px];
        #pragma unroll
        for (int i = 0; i < 32; i++) {
            int c = h*32 + i;
            xb[c*D_LD + px] = __float2bfloat16((yreg[i]-m)*rs*slnw[c] + slnb[c]);
        }
    }
    __syncthreads();

    // ---- conv4 (64->128) + fused SimpleGate -> Dst
    #pragma unroll
    for (int pi = 0; pi < 4; pi++) {
        int pc = pc0 + pi;
        wmma::fragment<wmma::accumulator, 16, 16, 16, float> accL, accH;
        wmma::fill_fragment(accL, 0.f);
        wmma::fill_fragment(accH, 0.f);
        #pragma unroll
        for (int kt = 0; kt < 4; kt++) {
            wmma::fragment<wmma::matrix_b, 16, 16, 16, __nv_bfloat16, wmma::row_major> bf;
            wmma::load_matrix_sync(bf, xb + (kt*16)*D_LD + pc*16, D_LD);
            wmma::fragment<wmma::matrix_a, 16, 16, 16, __nv_bfloat16, wmma::row_major> afL, afH;
            wmma::load_matrix_sync(afL, W4 + (r*16)*64 + kt*16, 64);
            wmma::load_matrix_sync(afH, W4 + ((r+4)*16)*64 + kt*16, 64);
            wmma::mma_sync(accL, afL, bf, accL);
            wmma::mma_sync(accH, afH, bf, accH);
        }
        wmma::store_matrix_sync(stgw,       accL, 16, wmma::mem_row_major);
        wmma::store_matrix_sync(stgw + 256, accH, 16, wmma::mem_row_major);
        __syncwarp();
        #pragma unroll
        for (int j = 0; j < 4; j++) {
            int lin = lane*4 + j;
            int row = lin >> 3, pr = lin & 7;
            int c = r*16 + row;
            float bL = sb4[c], bH = sb4[c + CC];
            float lo0 = stgw[row*16 + 2*pr]       + bL;
            float lo1 = stgw[row*16 + 2*pr + 1]   + bL;
            float hi0 = stgw[256 + row*16 + 2*pr]     + bH;
            float hi1 = stgw[256 + row*16 + 2*pr + 1] + bH;
            dstu[c*D_LDU + pc*8 + pr] = pack_bf16(lo0*hi0, lo1*hi1);
        }
        __syncwarp();
    }
    __syncthreads();

    // ---- conv5 (64->64): A from global, B = Dst (gated), out -> xb
    #pragma unroll
    for (int pi = 0; pi < 4; pi++) {
        int pc = pc0 + pi;
        wmma::fragment<wmma::accumulator, 16, 16, 16, float> acc;
        wmma::fill_fragment(acc, 0.f);
        #pragma unroll
        for (int kt = 0; kt < 4; kt++) {
            wmma::fragment<wmma::matrix_a, 16, 16, 16, __nv_bfloat16, wmma::row_major> af;
            wmma::fragment<wmma::matrix_b, 16, 16, 16, __nv_bfloat16, wmma::row_major> bf;
            wmma::load_matrix_sync(af, W5 + (r*16)*64 + kt*16, 64);
            wmma::load_matrix_sync(bf, Dst + (kt*16)*D_LD + pc*16, D_LD);
            wmma::mma_sync(acc, af, bf, acc);
        }
        wmma::store_matrix_sync(stgw, acc, 16, wmma::mem_row_major);
        __syncwarp();
        #pragma unroll
        for (int j = 0; j < 4; j++) {
            int lin = lane*4 + j;
            int row = lin >> 3, pr = lin & 7;
            xbu[(r*16+row)*D_LDU + pc*8 + pr] =
                pack_bf16(stgw[row*16 + 2*pr], stgw[row*16 + 2*pr + 1]);
        }
        __syncwarp();
    }
    __syncthreads();

    // out = y + (conv5 + b5) * gamma
    {
        float* OP = out + ((size_t)(b*CC + h*32))*HWP + pixbase + px;
        #pragma unroll
        for (int i = 0; i < 32; i++) {
            int c = h*32 + i;
            float d = __bfloat162float(xb[c*D_LD + px]);
            OP[(size_t)i*HWP] = yreg[i] + (d + sb5[c]) * sgamma[c];
        }
    }
}

// ---------------- launch ----------------
extern "C" void kernel_launch(void* const* d_in, const int* in_sizes, int n_in,
                              void* d_out, int out_size)
{
    const float* inp   = (const float*)d_in[0];
    const float* probs = (const float*)d_in[1];
    const float* ln1w  = (const float*)d_in[2];
    const float* ln1b  = (const float*)d_in[3];
    const float* ln2w  = (const float*)d_in[4];
    const float* ln2b  = (const float*)d_in[5];
    const float* w1    = (const float*)d_in[6];
    const float* b1    = (const float*)d_in[7];
    const float* la1   = (const float*)d_in[8];
    const float* lb1   = (const float*)d_in[9];
    const float* w2    = (const float*)d_in[10];
    const float* b2    = (const float*)d_in[11];
    const float* la2   = (const float*)d_in[12];
    const float* lb2   = (const float*)d_in[13];
    const float* wsca  = (const float*)d_in[14];
    const float* bsca  = (const float*)d_in[15];
    const float* la_s  = (const float*)d_in[16];
    const float* lb_s  = (const float*)d_in[17];
    const float* w3    = (const float*)d_in[18];
    const float* b3    = (const float*)d_in[19];
    const float* la3   = (const float*)d_in[20];
    const float* lb3   = (const float*)d_in[21];
    const float* w4    = (const float*)d_in[22];
    const float* b4    = (const float*)d_in[23];
    const float* la4   = (const float*)d_in[24];
    const float* lb4   = (const float*)d_in[25];
    const float* w5    = (const float*)d_in[26];
    const float* b5    = (const float*)d_in[27];
    const float* la5   = (const float*)d_in[28];
    const float* lb5   = (const float*)d_in[29];
    const float* beta  = (const float*)d_in[30];
    const float* gamma = (const float*)d_in[31];
    float* out = (float*)d_out;

    const int smem1 = DWC*W_LD*2 + CC*XB_LD*2 + 8*256*4
                    + (256+256+128+128+128+64+64)*4;
    const int smem4 = CC*D_LD*2*2 + 8*512*4
                    + (128+128+256+256+64+64+64+128+64+64+64+64+64)*4;  // 56832
    cudaFuncSetAttribute(k1_ln_conv1, cudaFuncAttributeMaxDynamicSharedMemorySize, smem1);
    cudaFuncSetAttribute(k4_final,    cudaFuncAttributeMaxDynamicSharedMemorySize, smem4);

    k0_weights<<<BB, 256>>>(probs, w1, la1, lb1, w3, la3, lb3,
                            w4, la4, lb4, w5, la5, lb5, wsca, la_s, lb_s);
    k1_ln_conv1<<<dim3(HWP/128, BB), 256, smem1>>>(inp, ln1w, ln1b, b1);
    k2_dw_gate_pool<<<dim3(HH/8, CC, BB), 256>>>(probs, w2, la2, lb2, b2);
    k4_final<<<dim3(HWP/TP4, BB), 256, smem4>>>(inp, bsca, b3, b4, b5,
                                                ln2w, ln2b, beta, gamma, out);
}